// round 7
// baseline (speedup 1.0000x reference)
#include <cuda_runtime.h>
#include <math.h>

#define Sq  2048
#define Dd  512
#define Hh  8
#define DHh 64
#define CWw 128
#define NSPLIT 4
#define KSPL (Dd / NSPLIT)    // 128

// ---------------- scratch (device globals) -------------------------------------
__device__ float g_cur[Sq * Dd];
__device__ float g_q[Sq * DHh];
__device__ float g_k[Sq * DHh];
__device__ float g_v[Sq * DHh];
__device__ float g_part[3][NSPLIT][Sq * DHh];   // split-K partials (6 MB)

// ---------------- cp.async helpers ----------------------------------------------
__device__ __forceinline__ unsigned smem_u32(const void* p) {
    return (unsigned)__cvta_generic_to_shared(p);
}
__device__ __forceinline__ void cp_async16(void* dst, const void* src) {
    asm volatile("cp.async.ca.shared.global [%0], [%1], 16;\n"
                 :: "r"(smem_u32(dst)), "l"(src));
}
#define CP_COMMIT() asm volatile("cp.async.commit_group;\n")
#define CP_WAIT(N)  asm volatile("cp.async.wait_group %0;\n" :: "n"(N))

// ---------------- init: cur = x -------------------------------------------------
__global__ void init_kernel(const float4* __restrict__ x) {
    int i = blockIdx.x * blockDim.x + threadIdx.x;
    ((float4*)g_cur)[i] = x[i];
}

// ---------------- qkv split-K partial GEMM (R6 proven) --------------------------
__global__ __launch_bounds__(128) void qkv_partial(const float* __restrict__ Wq,
                                                   const float* __restrict__ Wk,
                                                   const float* __restrict__ Wvd, int h)
{
    __shared__ float Xs[32][36];   // [k][m]
    __shared__ float Ws[32][68];   // [k][n]

    const int sel = blockIdx.y;
    const int sp  = blockIdx.z;
    const float* B = (sel == 0 ? Wq : sel == 1 ? Wk : Wvd) + (size_t)h * DHh * Dd;
    float* C = &g_part[sel][sp][0];
    const int m0 = blockIdx.x * 32;
    const int kb = sp * KSPL;

    const int t  = threadIdx.x;
    const int tx = t & 15;
    const int ty = t >> 4;

    float acc[4][4] = {};

    for (int k0 = kb; k0 < kb + KSPL; k0 += 32) {
        #pragma unroll
        for (int r = 0; r < 2; r++) {
            int f = t + r * 128;
            int m = f >> 3, kv = f & 7;
            float4 va = *(const float4*)&g_cur[(size_t)(m0 + m) * Dd + k0 + kv * 4];
            Xs[kv * 4 + 0][m] = va.x;
            Xs[kv * 4 + 1][m] = va.y;
            Xs[kv * 4 + 2][m] = va.z;
            Xs[kv * 4 + 3][m] = va.w;
        }
        #pragma unroll
        for (int r = 0; r < 4; r++) {
            int f = t + r * 128;
            int n = f >> 3, kv = f & 7;
            float4 vb = *(const float4*)&B[(size_t)n * Dd + k0 + kv * 4];
            Ws[kv * 4 + 0][n] = vb.x;
            Ws[kv * 4 + 1][n] = vb.y;
            Ws[kv * 4 + 2][n] = vb.z;
            Ws[kv * 4 + 3][n] = vb.w;
        }
        __syncthreads();

        #pragma unroll
        for (int k = 0; k < 32; k++) {
            float4 a4 = *(const float4*)&Xs[k][ty * 4];
            float4 b4 = *(const float4*)&Ws[k][tx * 4];
            float a[4] = {a4.x, a4.y, a4.z, a4.w};
            float b[4] = {b4.x, b4.y, b4.z, b4.w};
            #pragma unroll
            for (int i = 0; i < 4; i++)
                #pragma unroll
                for (int j = 0; j < 4; j++)
                    acc[i][j] = fmaf(a[i], b[j], acc[i][j]);
        }
        __syncthreads();
    }

    #pragma unroll
    for (int i = 0; i < 4; i++) {
        float4 o = make_float4(acc[i][0], acc[i][1], acc[i][2], acc[i][3]);
        *(float4*)&C[(size_t)(m0 + ty * 4 + i) * DHh + tx * 4] = o;
    }
}

// ---------------- reduce 4 partials -> g_q/g_k/g_v ------------------------------
__global__ void qkv_reduce()
{
    const int sel = blockIdx.y;
    const int i = blockIdx.x * 256 + threadIdx.x;
    float4 a = ((const float4*)&g_part[sel][0][0])[i];
    float4 b = ((const float4*)&g_part[sel][1][0])[i];
    float4 c = ((const float4*)&g_part[sel][2][0])[i];
    float4 d = ((const float4*)&g_part[sel][3][0])[i];
    float4 o;
    o.x = (a.x + b.x) + (c.x + d.x);
    o.y = (a.y + b.y) + (c.y + d.y);
    o.z = (a.z + b.z) + (c.z + d.z);
    o.w = (a.w + b.w) + (c.w + d.w);
    float* out = (sel == 0 ? g_q : sel == 1 ? g_k : g_v);
    ((float4*)out)[i] = o;
}

// ---------------- fused attn + up-projection + residual + renorm ----------------
// block = 16 tokens, 512 threads (16 warps, 1 query/token per warp).
#define KE2  272                     // K window rows: 256 + 16 - 1 -> pad 272
#define KP   68
#define PP   292
#define WCP  68
#define WCHUNK (128 * WCP)           // 8704 floats

#define SM_A   0                     // 18496 floats: Ks / Rs / W chunks
#define SM_PS  (KE2 * KP)            // 18496
#define SM_QS  (SM_PS + 16 * PP)     // 23168
#define SM_DS  (SM_QS + 16 * DHh)    // 24192
#define SM_TOT (SM_DS + 16 * DHh)    // 25216 floats = 100864 B

__global__ __launch_bounds__(512) void attn_upnorm(const float* __restrict__ Wvu,
                                                   int h, int last,
                                                   float* __restrict__ out)
{
    extern __shared__ float sm[];
    float* Ks = sm + SM_A;
    float* Ps = sm + SM_PS;
    float* Qs = sm + SM_QS;
    float* ds = sm + SM_DS;
    float* Rs = sm + SM_A;                  // AV partials (Ks dead)
    float* Wc[2] = { sm + SM_A, sm + SM_A + WCHUNK };

    const int t    = threadIdx.x;           // 512
    const int w    = t >> 5;                // 0..15
    const int lane = t & 31;
    const int j0   = blockIdx.x * 16;
    const int kb   = j0 - CWw;
    const float* W = Wvu + (size_t)h * Dd * DHh;

    // ---- load K window (272 rows) + Q tile
    for (int f = t; f < KE2 * 16; f += 512) {
        int kk = f >> 4, d4 = f & 15;
        int gk = kb + kk;
        float4 kv = make_float4(0.f, 0.f, 0.f, 0.f);
        if (gk >= 0 && gk < Sq) kv = ((const float4*)&g_k[(size_t)gk * DHh])[d4];
        *(float4*)&Ks[kk * KP + d4 * 4] = kv;
    }
    if (t < 256) {
        int q = t >> 4, d4 = t & 15;
        ((float4*)&Qs[q * DHh])[d4] = ((const float4*)&g_q[(size_t)(j0 + q) * DHh])[d4];
    }
    __syncthreads();

    // ---- scores: warp w owns query q = w; lane owns kk = lane + 32*jj (jj<9)
    {
        const int q = w;
        float a[9] = {};
        #pragma unroll
        for (int d4 = 0; d4 < 16; d4++) {
            float4 qa = *(const float4*)&Qs[q * DHh + d4 * 4];
            #pragma unroll
            for (int jj = 0; jj < 9; jj++) {
                int kk = lane + 32 * jj;
                int kks = kk < KE2 - 1 ? kk : KE2 - 1;   // clamp (masked anyway)
                const float4 kv = *(const float4*)&Ks[kks * KP + d4 * 4];
                a[jj] = fmaf(kv.x, qa.x, fmaf(kv.y, qa.y, fmaf(kv.z, qa.z, fmaf(kv.w, qa.w, a[jj]))));
            }
        }
        float mx = -1e30f;
        #pragma unroll
        for (int jj = 0; jj < 9; jj++) {
            int kk = lane + 32 * jj;
            int gk = kb + kk;
            bool ok = (gk >= 0) && (gk < Sq) && (kk >= q) && (kk < q + 256);
            a[jj] = ok ? a[jj] * 0.125f : -1e30f;
            mx = fmaxf(mx, a[jj]);
        }
        #pragma unroll
        for (int o = 16; o; o >>= 1) mx = fmaxf(mx, __shfl_xor_sync(0xffffffffu, mx, o));
        float s = 0.f;
        #pragma unroll
        for (int jj = 0; jj < 9; jj++) { a[jj] = __expf(a[jj] - mx); s += a[jj]; }
        #pragma unroll
        for (int o = 16; o; o >>= 1) s += __shfl_xor_sync(0xffffffffu, s, o);
        const float inv = 1.f / s;
        #pragma unroll
        for (int jj = 0; jj < 9; jj++)
            Ps[q * PP + lane + 32 * jj] = a[jj] * inv;
    }
    __syncthreads();   // Ps done; Ks dead

    // ---- AV: warp w owns keys [17w, 17w+17); V streamed from gmem (L2)
    {
        const int qh = (lane >> 4) * 8;
        const int d4 = lane & 15;
        float4 r[8] = {};
        #pragma unroll
        for (int i = 0; i < 17; i++) {
            int kk = w * 17 + i;
            int gk = kb + kk;
            float4 v4 = make_float4(0.f, 0.f, 0.f, 0.f);
            if (gk >= 0 && gk < Sq)
                v4 = ((const float4*)&g_v[(size_t)gk * DHh])[d4];
            #pragma unroll
            for (int qi = 0; qi < 8; qi++) {
                float p = Ps[(qh + qi) * PP + kk];
                r[qi].x = fmaf(p, v4.x, r[qi].x);
                r[qi].y = fmaf(p, v4.y, r[qi].y);
                r[qi].z = fmaf(p, v4.z, r[qi].z);
                r[qi].w = fmaf(p, v4.w, r[qi].w);
            }
        }
        #pragma unroll
        for (int qi = 0; qi < 8; qi++)
            *(float4*)&Rs[(w * 16 + qh + qi) * DHh + d4 * 4] = r[qi];
    }
    __syncthreads();

    // reduce 16 warp-partials -> ds (16 x 64)
    #pragma unroll
    for (int ii = 0; ii < 2; ii++) {
        int idx = t + 512 * ii;          // 0..1023
        int q = idx >> 6, d = idx & 63;
        float s = 0.f;
        #pragma unroll
        for (int ww = 0; ww < 16; ww++) s += Rs[(ww * 16 + q) * DHh + d];
        ds[q * DHh + d] = s;
    }
    __syncthreads();   // ds done; region A free for W chunks

    // ---- up-projection: W streamed in 4 chunks of 128 rows [n][k], double-buffered
    #pragma unroll
    for (int r = 0; r < 4; r++) {
        int f = t + r * 512;
        int row = f >> 4, k4 = f & 15;
        cp_async16(&Wc[0][row * WCP + k4 * 4], &W[(size_t)row * DHh + k4 * 4]);
    }
    CP_COMMIT();

    float acc[16] = {};   // 1 token (j0 + w), 16 n-columns

    for (int c = 0; c < 4; c++) {
        if (c < 3) {
            float* dst = Wc[(c + 1) & 1];
            const float* src = W + (size_t)(c + 1) * 128 * DHh;
            #pragma unroll
            for (int r = 0; r < 4; r++) {
                int f = t + r * 512;
                int row = f >> 4, k4 = f & 15;
                cp_async16(&dst[row * WCP + k4 * 4], &src[(size_t)row * DHh + k4 * 4]);
            }
            CP_COMMIT();
            CP_WAIT(1);
        } else {
            CP_WAIT(0);
        }
        __syncthreads();

        const float* Wb = Wc[c & 1];
        #pragma unroll
        for (int k4 = 0; k4 < 16; k4++) {
            float4 a0 = *(const float4*)&ds[w * DHh + k4 * 4];
            #pragma unroll
            for (int r = 0; r < 4; r++) {
                float4 wv = *(const float4*)&Wb[(lane + 32 * r) * WCP + k4 * 4];
                float s0 = acc[c * 4 + r];
                s0 = fmaf(a0.x, wv.x, s0);
                s0 = fmaf(a0.y, wv.y, s0);
                s0 = fmaf(a0.z, wv.z, s0);
                s0 = fmaf(a0.w, wv.w, s0);
                acc[c * 4 + r] = s0;
            }
        }
        __syncthreads();
    }

    // ---- residual + renorm, 1 token per warp
    {
        const int m = j0 + w;
        float cres[16], y[16];
        float s = 0.f;
        #pragma unroll
        for (int j = 0; j < 16; j++) {
            int n = (j >> 2) * 128 + lane + 32 * (j & 3);
            cres[j] = g_cur[(size_t)m * Dd + n];
            y[j] = acc[j] + cres[j];
            s += y[j];
        }
        #pragma unroll
        for (int o = 16; o; o >>= 1) s += __shfl_xor_sync(0xffffffffu, s, o);
        float im = 512.f / s;                       // 1/m1
        s = 0.f;
        #pragma unroll
        for (int j = 0; j < 16; j++) { y[j] *= im; s += y[j]; }
        #pragma unroll
        for (int o = 16; o; o >>= 1) s += __shfl_xor_sync(0xffffffffu, s, o);
        float m2 = s * (1.f / 512.f);
        float v = 0.f;
        #pragma unroll
        for (int j = 0; j < 16; j++) { y[j] -= m2; v += y[j] * y[j]; }
        #pragma unroll
        for (int o = 16; o; o >>= 1) v += __shfl_xor_sync(0xffffffffu, v, o);
        float is = rsqrtf(v * (1.f / 511.f));

        #pragma unroll
        for (int j = 0; j < 16; j++) {
            int n = (j >> 2) * 128 + lane + 32 * (j & 3);
            float nv = cres[j] + y[j] * is + m2;
            g_cur[(size_t)m * Dd + n] = nv;
            if (last) out[(size_t)m * Dd + n] = nv * 0.125f;
        }
    }
}

// ---------------- launch ---------------------------------------------------------
extern "C" void kernel_launch(void* const* d_in, const int* in_sizes, int n_in,
                              void* d_out, int out_size)
{
    const float* x   = (const float*)d_in[0];
    const float* Wq  = (const float*)d_in[1];
    const float* Wk  = (const float*)d_in[2];
    const float* Wvd = (const float*)d_in[3];
    const float* Wvu = (const float*)d_in[4];
    float* out = (float*)d_out;

    const int fused_smem = SM_TOT * 4;   // 100864 B
    cudaFuncSetAttribute(attn_upnorm, cudaFuncAttributeMaxDynamicSharedMemorySize, fused_smem);

    init_kernel<<<(Sq * Dd / 4) / 256, 256>>>((const float4*)x);
    for (int h = 0; h < Hh; h++) {
        qkv_partial<<<dim3(Sq / 32, 3, NSPLIT), 128>>>(Wq, Wk, Wvd, h);
        qkv_reduce<<<dim3(Sq * DHh / 4 / 256, 3), 256>>>();
        attn_upnorm<<<Sq / 16, 512, fused_smem>>>(Wvu, h, h == Hh - 1 ? 1 : 0, out);
    }
}

// round 8
// speedup vs baseline: 1.0273x; 1.0273x over previous
#include <cuda_runtime.h>
#include <math.h>

#define Sq  2048
#define Dd  512
#define Hh  8
#define DHh 64
#define CWw 128
#define NSPLIT 4
#define KSPL (Dd / NSPLIT)    // 128

// ---------------- scratch (device globals) -------------------------------------
__device__ float g_cur[Sq * Dd];
__device__ float g_q[Sq * DHh];
__device__ float g_k[Sq * DHh];
__device__ float g_v[Sq * DHh];
__device__ float g_part[3][NSPLIT][Sq * DHh];

// ---------------- cp.async helpers ----------------------------------------------
__device__ __forceinline__ unsigned smem_u32(const void* p) {
    return (unsigned)__cvta_generic_to_shared(p);
}
__device__ __forceinline__ void cp_async16(void* dst, const void* src) {
    asm volatile("cp.async.ca.shared.global [%0], [%1], 16;\n"
                 :: "r"(smem_u32(dst)), "l"(src));
}
#define CP_COMMIT() asm volatile("cp.async.commit_group;\n")
#define CP_WAIT(N)  asm volatile("cp.async.wait_group %0;\n" :: "n"(N))

// ---------------- init: cur = x -------------------------------------------------
__global__ void init_kernel(const float4* __restrict__ x) {
    int i = blockIdx.x * blockDim.x + threadIdx.x;
    ((float4*)g_cur)[i] = x[i];
}

// ---------------- qkv split-K partial GEMM (R6 proven, at fp32 floor) -----------
__global__ __launch_bounds__(128) void qkv_partial(const float* __restrict__ Wq,
                                                   const float* __restrict__ Wk,
                                                   const float* __restrict__ Wvd, int h)
{
    __shared__ float Xs[32][36];
    __shared__ float Ws[32][68];

    const int sel = blockIdx.y;
    const int sp  = blockIdx.z;
    const float* B = (sel == 0 ? Wq : sel == 1 ? Wk : Wvd) + (size_t)h * DHh * Dd;
    float* C = &g_part[sel][sp][0];
    const int m0 = blockIdx.x * 32;
    const int kb = sp * KSPL;

    const int t  = threadIdx.x;
    const int tx = t & 15;
    const int ty = t >> 4;

    float acc[4][4] = {};

    for (int k0 = kb; k0 < kb + KSPL; k0 += 32) {
        #pragma unroll
        for (int r = 0; r < 2; r++) {
            int f = t + r * 128;
            int m = f >> 3, kv = f & 7;
            float4 va = *(const float4*)&g_cur[(size_t)(m0 + m) * Dd + k0 + kv * 4];
            Xs[kv * 4 + 0][m] = va.x;
            Xs[kv * 4 + 1][m] = va.y;
            Xs[kv * 4 + 2][m] = va.z;
            Xs[kv * 4 + 3][m] = va.w;
        }
        #pragma unroll
        for (int r = 0; r < 4; r++) {
            int f = t + r * 128;
            int n = f >> 3, kv = f & 7;
            float4 vb = *(const float4*)&B[(size_t)n * Dd + k0 + kv * 4];
            Ws[kv * 4 + 0][n] = vb.x;
            Ws[kv * 4 + 1][n] = vb.y;
            Ws[kv * 4 + 2][n] = vb.z;
            Ws[kv * 4 + 3][n] = vb.w;
        }
        __syncthreads();

        #pragma unroll
        for (int k = 0; k < 32; k++) {
            float4 a4 = *(const float4*)&Xs[k][ty * 4];
            float4 b4 = *(const float4*)&Ws[k][tx * 4];
            float a[4] = {a4.x, a4.y, a4.z, a4.w};
            float b[4] = {b4.x, b4.y, b4.z, b4.w};
            #pragma unroll
            for (int i = 0; i < 4; i++)
                #pragma unroll
                for (int j = 0; j < 4; j++)
                    acc[i][j] = fmaf(a[i], b[j], acc[i][j]);
        }
        __syncthreads();
    }

    #pragma unroll
    for (int i = 0; i < 4; i++) {
        float4 o = make_float4(acc[i][0], acc[i][1], acc[i][2], acc[i][3]);
        *(float4*)&C[(size_t)(m0 + ty * 4 + i) * DHh + tx * 4] = o;
    }
}

__global__ void qkv_reduce()
{
    const int sel = blockIdx.y;
    const int i = blockIdx.x * 256 + threadIdx.x;
    float4 a = ((const float4*)&g_part[sel][0][0])[i];
    float4 b = ((const float4*)&g_part[sel][1][0])[i];
    float4 c = ((const float4*)&g_part[sel][2][0])[i];
    float4 d = ((const float4*)&g_part[sel][3][0])[i];
    float4 o;
    o.x = (a.x + b.x) + (c.x + d.x);
    o.y = (a.y + b.y) + (c.y + d.y);
    o.z = (a.z + b.z) + (c.z + d.z);
    o.w = (a.w + b.w) + (c.w + d.w);
    float* out = (sel == 0 ? g_q : sel == 1 ? g_k : g_v);
    ((float4*)out)[i] = o;
}

// ---------------- fused attn + up-proj + residual + renorm ----------------------
// block = 8 tokens, 256 threads (8 warps, 1 query/warp), grid = 256 (2 blocks/SM)
#define NT   8                       // tokens per block
#define KE2  264                     // K rows staged: 256 + NT - 1 = 263, pad 264
#define KP   68
#define PP   292
#define WCP  68
#define WCHUNK (128 * WCP)           // 8704 floats

#define SM_A   0                     // 17952 floats: Ks / Rs / W chunks
#define SM_PS  (KE2 * KP)            // 17952
#define SM_QS  (SM_PS + NT * PP)     // +2336
#define SM_DS  (SM_QS + NT * DHh)    // +512
#define SM_TOT (SM_DS + NT * DHh)    // 21312 floats = 85248 B

__global__ __launch_bounds__(256) void attn_upnorm(const float* __restrict__ Wvu,
                                                   int h, int last,
                                                   float* __restrict__ out)
{
    extern __shared__ float sm[];
    float* Ks = sm + SM_A;
    float* Ps = sm + SM_PS;
    float* Qs = sm + SM_QS;
    float* ds = sm + SM_DS;
    float* Rs = sm + SM_A;                  // AV partials (Ks dead): [8][8][64]
    float* Wc[2] = { sm + SM_A, sm + SM_A + WCHUNK };

    const int t    = threadIdx.x;           // 256
    const int w    = t >> 5;                // 0..7
    const int lane = t & 31;
    const int j0   = blockIdx.x * NT;
    const int kb   = j0 - CWw;
    const float* W = Wvu + (size_t)h * Dd * DHh;

    // ---- load K window (264 rows) + Q tile (8 x 64)
    for (int f = t; f < KE2 * 16; f += 256) {
        int kk = f >> 4, d4 = f & 15;
        int gk = kb + kk;
        float4 kv = make_float4(0.f, 0.f, 0.f, 0.f);
        if (gk >= 0 && gk < Sq) kv = ((const float4*)&g_k[(size_t)gk * DHh])[d4];
        *(float4*)&Ks[kk * KP + d4 * 4] = kv;
    }
    if (t < NT * 16) {
        int q = t >> 4, d4 = t & 15;
        ((float4*)&Qs[q * DHh])[d4] = ((const float4*)&g_q[(size_t)(j0 + q) * DHh])[d4];
    }
    __syncthreads();

    // ---- scores: warp w owns query q = w; lane owns kk = lane + 32*jj (jj<9)
    {
        const int q = w;
        float a[9] = {};
        #pragma unroll
        for (int d4 = 0; d4 < 16; d4++) {
            float4 qa = *(const float4*)&Qs[q * DHh + d4 * 4];
            #pragma unroll
            for (int jj = 0; jj < 9; jj++) {
                int kk = lane + 32 * jj;
                int kks = kk < KE2 - 1 ? kk : KE2 - 1;   // clamp (masked below)
                const float4 kv = *(const float4*)&Ks[kks * KP + d4 * 4];
                a[jj] = fmaf(kv.x, qa.x, fmaf(kv.y, qa.y, fmaf(kv.z, qa.z, fmaf(kv.w, qa.w, a[jj]))));
            }
        }
        float mx = -1e30f;
        #pragma unroll
        for (int jj = 0; jj < 9; jj++) {
            int kk = lane + 32 * jj;
            int gk = kb + kk;
            bool ok = (gk >= 0) && (gk < Sq) && (kk >= q) && (kk < q + 256);
            a[jj] = ok ? a[jj] * 0.125f : -1e30f;
            mx = fmaxf(mx, a[jj]);
        }
        #pragma unroll
        for (int o = 16; o; o >>= 1) mx = fmaxf(mx, __shfl_xor_sync(0xffffffffu, mx, o));
        float s = 0.f;
        #pragma unroll
        for (int jj = 0; jj < 9; jj++) { a[jj] = __expf(a[jj] - mx); s += a[jj]; }
        #pragma unroll
        for (int o = 16; o; o >>= 1) s += __shfl_xor_sync(0xffffffffu, s, o);
        const float inv = 1.f / s;
        #pragma unroll
        for (int jj = 0; jj < 9; jj++) {
            int kk = lane + 32 * jj;
            if (kk < KE2) Ps[q * PP + kk] = a[jj] * inv;
        }
    }
    __syncthreads();   // Ps done; Ks dead

    // ---- AV: warp w owns keys [33w, 33w+33); V streamed from gmem (L2)
    {
        const int qh = (lane >> 4) * 4;       // queries qh..qh+3 per half-warp
        const int d4 = lane & 15;
        float4 r[4] = {};
        #pragma unroll
        for (int i = 0; i < 33; i++) {
            int kk = w * 33 + i;
            int gk = kb + kk;
            float4 v4 = make_float4(0.f, 0.f, 0.f, 0.f);
            if (gk >= 0 && gk < Sq)
                v4 = ((const float4*)&g_v[(size_t)gk * DHh])[d4];
            #pragma unroll
            for (int qi = 0; qi < 4; qi++) {
                float p = Ps[(qh + qi) * PP + kk];
                r[qi].x = fmaf(p, v4.x, r[qi].x);
                r[qi].y = fmaf(p, v4.y, r[qi].y);
                r[qi].z = fmaf(p, v4.z, r[qi].z);
                r[qi].w = fmaf(p, v4.w, r[qi].w);
            }
        }
        #pragma unroll
        for (int qi = 0; qi < 4; qi++)
            *(float4*)&Rs[(w * NT + qh + qi) * DHh + d4 * 4] = r[qi];
    }
    __syncthreads();

    // reduce 8 warp-partials -> ds (8 x 64); 512 outputs, 256 threads x 2
    #pragma unroll
    for (int ii = 0; ii < 2; ii++) {
        int idx = t + 256 * ii;
        int q = idx >> 6, d = idx & 63;
        float s = 0.f;
        #pragma unroll
        for (int ww = 0; ww < 8; ww++) s += Rs[(ww * NT + q) * DHh + d];
        ds[q * DHh + d] = s;
    }
    __syncthreads();   // ds done; region A free for W chunks

    // ---- up-projection: W streamed in 4 chunks of 128 rows [n][k], double-buffered
    #pragma unroll
    for (int r = 0; r < 8; r++) {
        int f = t + r * 256;
        int row = f >> 4, k4 = f & 15;
        cp_async16(&Wc[0][row * WCP + k4 * 4], &W[(size_t)row * DHh + k4 * 4]);
    }
    CP_COMMIT();

    float acc[16] = {};   // token j0 + w, 16 n-columns per lane

    for (int c = 0; c < 4; c++) {
        if (c < 3) {
            float* dst = Wc[(c + 1) & 1];
            const float* src = W + (size_t)(c + 1) * 128 * DHh;
            #pragma unroll
            for (int r = 0; r < 8; r++) {
                int f = t + r * 256;
                int row = f >> 4, k4 = f & 15;
                cp_async16(&dst[row * WCP + k4 * 4], &src[(size_t)row * DHh + k4 * 4]);
            }
            CP_COMMIT();
            CP_WAIT(1);
        } else {
            CP_WAIT(0);
        }
        __syncthreads();

        const float* Wb = Wc[c & 1];
        #pragma unroll
        for (int k4 = 0; k4 < 16; k4++) {
            float4 a0 = *(const float4*)&ds[w * DHh + k4 * 4];
            #pragma unroll
            for (int r = 0; r < 4; r++) {
                float4 wv = *(const float4*)&Wb[(lane + 32 * r) * WCP + k4 * 4];
                float s0 = acc[c * 4 + r];
                s0 = fmaf(a0.x, wv.x, s0);
                s0 = fmaf(a0.y, wv.y, s0);
                s0 = fmaf(a0.z, wv.z, s0);
                s0 = fmaf(a0.w, wv.w, s0);
                acc[c * 4 + r] = s0;
            }
        }
        __syncthreads();
    }

    // ---- residual + renorm, 1 token per warp
    {
        const int m = j0 + w;
        float cres[16], y[16];
        float s = 0.f;
        #pragma unroll
        for (int j = 0; j < 16; j++) {
            int n = (j >> 2) * 128 + lane + 32 * (j & 3);
            cres[j] = g_cur[(size_t)m * Dd + n];
            y[j] = acc[j] + cres[j];
            s += y[j];
        }
        #pragma unroll
        for (int o = 16; o; o >>= 1) s += __shfl_xor_sync(0xffffffffu, s, o);
        float im = 512.f / s;                       // 1/m1
        s = 0.f;
        #pragma unroll
        for (int j = 0; j < 16; j++) { y[j] *= im; s += y[j]; }
        #pragma unroll
        for (int o = 16; o; o >>= 1) s += __shfl_xor_sync(0xffffffffu, s, o);
        float m2 = s * (1.f / 512.f);
        float v = 0.f;
        #pragma unroll
        for (int j = 0; j < 16; j++) { y[j] -= m2; v += y[j] * y[j]; }
        #pragma unroll
        for (int o = 16; o; o >>= 1) v += __shfl_xor_sync(0xffffffffu, v, o);
        float is = rsqrtf(v * (1.f / 511.f));

        #pragma unroll
        for (int j = 0; j < 16; j++) {
            int n = (j >> 2) * 128 + lane + 32 * (j & 3);
            float nv = cres[j] + y[j] * is + m2;
            g_cur[(size_t)m * Dd + n] = nv;
            if (last) out[(size_t)m * Dd + n] = nv * 0.125f;
        }
    }
}

// ---------------- launch ---------------------------------------------------------
extern "C" void kernel_launch(void* const* d_in, const int* in_sizes, int n_in,
                              void* d_out, int out_size)
{
    const float* x   = (const float*)d_in[0];
    const float* Wq  = (const float*)d_in[1];
    const float* Wk  = (const float*)d_in[2];
    const float* Wvd = (const float*)d_in[3];
    const float* Wvu = (const float*)d_in[4];
    float* out = (float*)d_out;

    const int fused_smem = SM_TOT * 4;   // 85248 B -> 2 blocks/SM
    cudaFuncSetAttribute(attn_upnorm, cudaFuncAttributeMaxDynamicSharedMemorySize, fused_smem);

    init_kernel<<<(Sq * Dd / 4) / 256, 256>>>((const float4*)x);
    for (int h = 0; h < Hh; h++) {
        qkv_partial<<<dim3(Sq / 32, 3, NSPLIT), 128>>>(Wq, Wk, Wvd, h);
        qkv_reduce<<<dim3(Sq * DHh / 4 / 256, 3), 256>>>();
        attn_upnorm<<<Sq / NT, 256, fused_smem>>>(Wvu, h, h == Hh - 1 ? 1 : 0, out);
    }
}

// round 9
// speedup vs baseline: 1.0365x; 1.0090x over previous
#include <cuda_runtime.h>
#include <math.h>

#define Sq  2048
#define Dd  512
#define Hh  8
#define DHh 64
#define CWw 128
#define NSPLIT 4
#define KSPL (Dd / NSPLIT)    // 128

// ---------------- scratch (device globals) -------------------------------------
__device__ float g_cur[Sq * Dd];
__device__ float g_q[Sq * DHh];
__device__ float g_k[Sq * DHh];
__device__ float g_v[Sq * DHh];
__device__ float g_part[3][NSPLIT][Sq * DHh];
__device__ float g_pm[2][Sq];            // partial softmax max
__device__ float g_ps[2][Sq];            // partial softmax sum(exp)
__device__ float g_pv[2][Sq * DHh];      // partial sum(exp * V)

// ---------------- cp.async helpers ----------------------------------------------
__device__ __forceinline__ unsigned smem_u32(const void* p) {
    return (unsigned)__cvta_generic_to_shared(p);
}
__device__ __forceinline__ void cp_async16(void* dst, const void* src) {
    asm volatile("cp.async.ca.shared.global [%0], [%1], 16;\n"
                 :: "r"(smem_u32(dst)), "l"(src));
}
#define CP_COMMIT() asm volatile("cp.async.commit_group;\n")
#define CP_WAIT(N)  asm volatile("cp.async.wait_group %0;\n" :: "n"(N))

// ---------------- init: cur = x -------------------------------------------------
__global__ void init_kernel(const float4* __restrict__ x) {
    int i = blockIdx.x * blockDim.x + threadIdx.x;
    ((float4*)g_cur)[i] = x[i];
}

// ---------------- qkv split-K partial GEMM (proven, at fp32 floor) --------------
__global__ __launch_bounds__(128) void qkv_partial(const float* __restrict__ Wq,
                                                   const float* __restrict__ Wk,
                                                   const float* __restrict__ Wvd, int h)
{
    __shared__ float Xs[32][36];
    __shared__ float Ws[32][68];

    const int sel = blockIdx.y;
    const int sp  = blockIdx.z;
    const float* B = (sel == 0 ? Wq : sel == 1 ? Wk : Wvd) + (size_t)h * DHh * Dd;
    float* C = &g_part[sel][sp][0];
    const int m0 = blockIdx.x * 32;
    const int kb = sp * KSPL;

    const int t  = threadIdx.x;
    const int tx = t & 15;
    const int ty = t >> 4;

    float acc[4][4] = {};

    for (int k0 = kb; k0 < kb + KSPL; k0 += 32) {
        #pragma unroll
        for (int r = 0; r < 2; r++) {
            int f = t + r * 128;
            int m = f >> 3, kv = f & 7;
            float4 va = *(const float4*)&g_cur[(size_t)(m0 + m) * Dd + k0 + kv * 4];
            Xs[kv * 4 + 0][m] = va.x;
            Xs[kv * 4 + 1][m] = va.y;
            Xs[kv * 4 + 2][m] = va.z;
            Xs[kv * 4 + 3][m] = va.w;
        }
        #pragma unroll
        for (int r = 0; r < 4; r++) {
            int f = t + r * 128;
            int n = f >> 3, kv = f & 7;
            float4 vb = *(const float4*)&B[(size_t)n * Dd + k0 + kv * 4];
            Ws[kv * 4 + 0][n] = vb.x;
            Ws[kv * 4 + 1][n] = vb.y;
            Ws[kv * 4 + 2][n] = vb.z;
            Ws[kv * 4 + 3][n] = vb.w;
        }
        __syncthreads();

        #pragma unroll
        for (int k = 0; k < 32; k++) {
            float4 a4 = *(const float4*)&Xs[k][ty * 4];
            float4 b4 = *(const float4*)&Ws[k][tx * 4];
            float a[4] = {a4.x, a4.y, a4.z, a4.w};
            float b[4] = {b4.x, b4.y, b4.z, b4.w};
            #pragma unroll
            for (int i = 0; i < 4; i++)
                #pragma unroll
                for (int j = 0; j < 4; j++)
                    acc[i][j] = fmaf(a[i], b[j], acc[i][j]);
        }
        __syncthreads();
    }

    #pragma unroll
    for (int i = 0; i < 4; i++) {
        float4 o = make_float4(acc[i][0], acc[i][1], acc[i][2], acc[i][3]);
        *(float4*)&C[(size_t)(m0 + ty * 4 + i) * DHh + tx * 4] = o;
    }
}

__global__ void qkv_reduce()
{
    const int sel = blockIdx.y;
    const int i = blockIdx.x * 256 + threadIdx.x;
    float4 a = ((const float4*)&g_part[sel][0][0])[i];
    float4 b = ((const float4*)&g_part[sel][1][0])[i];
    float4 c = ((const float4*)&g_part[sel][2][0])[i];
    float4 d = ((const float4*)&g_part[sel][3][0])[i];
    float4 o;
    o.x = (a.x + b.x) + (c.x + d.x);
    o.y = (a.y + b.y) + (c.y + d.y);
    o.z = (a.z + b.z) + (c.z + d.z);
    o.w = (a.w + b.w) + (c.w + d.w);
    float* out = (sel == 0 ? g_q : sel == 1 ? g_k : g_v);
    ((float4*)out)[i] = o;
}

// ---------------- attention, window-split halves ---------------------------------
// grid (S/16, 2): blockIdx.y = window half. 16 tokens, 256 threads.
// Half h covers window slots s in [128h, 128h+128) -> local keys kk in [q, q+128),
// key base kstart = j0 - 128 + 128h. Emits unnormalized (m, sum, sum(e*V)).
#define HT   16
#define KH   144      // rows staged: 127 + 15 + 1 -> pad 144
#define KHP  68
#define PP2  148

#define ASM_K  0
#define ASM_P  (KH * KHP)            // 9792
#define ASM_Q  (ASM_P + HT * PP2)    // +2368
#define ASM_T  (ASM_Q + HT * DHh)    // 13184 floats = 52736 B

__global__ __launch_bounds__(256) void attn_half()
{
    extern __shared__ float sm[];
    float* Ks = sm + ASM_K;
    float* Ps = sm + ASM_P;
    float* Qs = sm + ASM_Q;
    float* Rs = sm + ASM_K;          // AV partials overlay Ks (8*16*64 = 8192 <= 9792)

    const int t    = threadIdx.x;    // 256
    const int w    = t >> 5;
    const int lane = t & 31;
    const int j0   = blockIdx.x * HT;
    const int hf   = blockIdx.y;
    const int kstart = j0 - CWw + 128 * hf;

    // ---- stage K segment (144 rows, zero-filled OOB) + Q tile
    for (int f = t; f < KH * 16; f += 256) {
        int kk = f >> 4, d4 = f & 15;
        int gk = kstart + kk;
        float4 kv = make_float4(0.f, 0.f, 0.f, 0.f);
        if (gk >= 0 && gk < Sq) kv = ((const float4*)&g_k[(size_t)gk * DHh])[d4];
        *(float4*)&Ks[kk * KHP + d4 * 4] = kv;
    }
    {
        int q = t >> 4, d4 = t & 15;
        ((float4*)&Qs[q * DHh])[d4] = ((const float4*)&g_q[(size_t)(j0 + q) * DHh])[d4];
    }
    __syncthreads();

    // ---- scores: warp w owns queries q0=2w, q1=2w+1; shared slots kk=lane+32jj, jj<5
    const int q0 = 2 * w, q1 = 2 * w + 1;
    {
        float a0[5] = {}, a1[5] = {};
        #pragma unroll
        for (int d4 = 0; d4 < 16; d4++) {
            float4 qa = *(const float4*)&Qs[q0 * DHh + d4 * 4];
            float4 qb = *(const float4*)&Qs[q1 * DHh + d4 * 4];
            #pragma unroll
            for (int jj = 0; jj < 5; jj++) {
                int kk = lane + 32 * jj;
                int kks = kk < KH - 1 ? kk : KH - 1;   // clamp (masked below)
                const float4 kv = *(const float4*)&Ks[kks * KHP + d4 * 4];
                a0[jj] = fmaf(kv.x, qa.x, fmaf(kv.y, qa.y, fmaf(kv.z, qa.z, fmaf(kv.w, qa.w, a0[jj]))));
                a1[jj] = fmaf(kv.x, qb.x, fmaf(kv.y, qb.y, fmaf(kv.z, qb.z, fmaf(kv.w, qb.w, a1[jj]))));
            }
        }
        float m0 = -1e30f, m1 = -1e30f;
        #pragma unroll
        for (int jj = 0; jj < 5; jj++) {
            int kk = lane + 32 * jj;
            int gk = kstart + kk;
            bool gok = (gk >= 0) && (gk < Sq);
            bool v0 = gok && (kk >= q0) && (kk < q0 + 128);
            bool v1 = gok && (kk >= q1) && (kk < q1 + 128);
            a0[jj] = v0 ? a0[jj] * 0.125f : -1e30f;
            a1[jj] = v1 ? a1[jj] * 0.125f : -1e30f;
            m0 = fmaxf(m0, a0[jj]);
            m1 = fmaxf(m1, a1[jj]);
        }
        #pragma unroll
        for (int o = 16; o; o >>= 1) {
            m0 = fmaxf(m0, __shfl_xor_sync(0xffffffffu, m0, o));
            m1 = fmaxf(m1, __shfl_xor_sync(0xffffffffu, m1, o));
        }
        float s0 = 0.f, s1 = 0.f;
        #pragma unroll
        for (int jj = 0; jj < 5; jj++) {
            int kk = lane + 32 * jj;
            // exp of masked slots: a - m <= -1e29 -> expf underflows to 0
            float e0 = __expf(a0[jj] - m0);
            float e1 = __expf(a1[jj] - m1);
            s0 += e0;
            s1 += e1;
            if (kk < KH) {
                Ps[q0 * PP2 + kk] = e0;
                Ps[q1 * PP2 + kk] = e1;
            }
        }
        #pragma unroll
        for (int o = 16; o; o >>= 1) {
            s0 += __shfl_xor_sync(0xffffffffu, s0, o);
            s1 += __shfl_xor_sync(0xffffffffu, s1, o);
        }
        if (lane == 0) {
            g_pm[hf][j0 + q0] = m0;
            g_pm[hf][j0 + q1] = m1;
            g_ps[hf][j0 + q0] = s0;
            g_ps[hf][j0 + q1] = s1;
        }
    }
    __syncthreads();   // Ps done; Ks dead

    // ---- AV (unnormalized): warp w owns keys [18w, 18w+18); V streamed from L2
    {
        const int qh = (lane >> 4) * 8;
        const int d4 = lane & 15;
        float4 r[8] = {};
        #pragma unroll
        for (int i = 0; i < 18; i++) {
            int kk = w * 18 + i;
            int gk = kstart + kk;
            float4 v4 = make_float4(0.f, 0.f, 0.f, 0.f);
            if (gk >= 0 && gk < Sq)
                v4 = ((const float4*)&g_v[(size_t)gk * DHh])[d4];
            #pragma unroll
            for (int qi = 0; qi < 8; qi++) {
                float p = Ps[(qh + qi) * PP2 + kk];
                r[qi].x = fmaf(p, v4.x, r[qi].x);
                r[qi].y = fmaf(p, v4.y, r[qi].y);
                r[qi].z = fmaf(p, v4.z, r[qi].z);
                r[qi].w = fmaf(p, v4.w, r[qi].w);
            }
        }
        #pragma unroll
        for (int qi = 0; qi < 8; qi++)
            *(float4*)&Rs[(w * HT + qh + qi) * DHh + d4 * 4] = r[qi];
    }
    __syncthreads();

    // reduce 8 warp-partials -> g_pv (16 x 64)
    #pragma unroll
    for (int ii = 0; ii < 4; ii++) {
        int idx = t + 256 * ii;          // 0..1023
        int q = idx >> 6, d = idx & 63;
        float s = 0.f;
        #pragma unroll
        for (int ww = 0; ww < 8; ww++) s += Rs[(ww * HT + q) * DHh + d];
        g_pv[hf][(size_t)(j0 + q) * DHh + d] = s;
    }
}

// ---------------- fused combine + up-projection + residual + renorm -------------
// 8 tokens/block, 256 threads, grid 256. W streamed in 4 chunks double-buffered.
#define NT   8
#define WCP  68
#define WCHUNK (128 * WCP)           // 8704 floats

__global__ __launch_bounds__(256) void upnorm_kernel(const float* __restrict__ Wvu,
                                                     int h, int last,
                                                     float* __restrict__ out)
{
    extern __shared__ float sm[];
    float* Wc[2] = { sm, sm + WCHUNK };
    float* ds = sm + 2 * WCHUNK;     // [8][64]

    const int t    = threadIdx.x;    // 256
    const int w    = t >> 5;
    const int lane = t & 31;
    const int j0   = blockIdx.x * NT;
    const float* W = Wvu + (size_t)h * Dd * DHh;

    // ---- stage W chunk 0
    #pragma unroll
    for (int r = 0; r < 8; r++) {
        int f = t + r * 256;
        int row = f >> 4, k4 = f & 15;
        cp_async16(&Wc[0][row * WCP + k4 * 4], &W[(size_t)row * DHh + k4 * 4]);
    }
    CP_COMMIT();

    // ---- combine the two softmax halves -> ds (8 x 64)
    #pragma unroll
    for (int ii = 0; ii < 2; ii++) {
        int idx = t + 256 * ii;          // 0..511
        int q = idx >> 6, d = idx & 63;
        int m = j0 + q;
        float m0 = g_pm[0][m], m1 = g_pm[1][m];
        float M  = fmaxf(m0, m1);
        float c0 = __expf(m0 - M), c1 = __expf(m1 - M);
        float denom = c0 * g_ps[0][m] + c1 * g_ps[1][m];
        float pv = c0 * g_pv[0][(size_t)m * DHh + d] + c1 * g_pv[1][(size_t)m * DHh + d];
        ds[q * DHh + d] = pv / denom;
    }
    __syncthreads();

    float acc[16] = {};   // token j0 + w, 16 n-columns per lane

    for (int c = 0; c < 4; c++) {
        if (c < 3) {
            float* dst = Wc[(c + 1) & 1];
            const float* src = W + (size_t)(c + 1) * 128 * DHh;
            #pragma unroll
            for (int r = 0; r < 8; r++) {
                int f = t + r * 256;
                int row = f >> 4, k4 = f & 15;
                cp_async16(&dst[row * WCP + k4 * 4], &src[(size_t)row * DHh + k4 * 4]);
            }
            CP_COMMIT();
            CP_WAIT(1);
        } else {
            CP_WAIT(0);
        }
        __syncthreads();

        const float* Wb = Wc[c & 1];
        #pragma unroll
        for (int k4 = 0; k4 < 16; k4++) {
            float4 a0 = *(const float4*)&ds[w * DHh + k4 * 4];
            #pragma unroll
            for (int r = 0; r < 4; r++) {
                float4 wv = *(const float4*)&Wb[(lane + 32 * r) * WCP + k4 * 4];
                float s0 = acc[c * 4 + r];
                s0 = fmaf(a0.x, wv.x, s0);
                s0 = fmaf(a0.y, wv.y, s0);
                s0 = fmaf(a0.z, wv.z, s0);
                s0 = fmaf(a0.w, wv.w, s0);
                acc[c * 4 + r] = s0;
            }
        }
        __syncthreads();
    }

    // ---- residual + renorm, 1 token per warp
    {
        const int m = j0 + w;
        float cres[16], y[16];
        float s = 0.f;
        #pragma unroll
        for (int j = 0; j < 16; j++) {
            int n = (j >> 2) * 128 + lane + 32 * (j & 3);
            cres[j] = g_cur[(size_t)m * Dd + n];
            y[j] = acc[j] + cres[j];
            s += y[j];
        }
        #pragma unroll
        for (int o = 16; o; o >>= 1) s += __shfl_xor_sync(0xffffffffu, s, o);
        float im = 512.f / s;                       // 1/m1
        s = 0.f;
        #pragma unroll
        for (int j = 0; j < 16; j++) { y[j] *= im; s += y[j]; }
        #pragma unroll
        for (int o = 16; o; o >>= 1) s += __shfl_xor_sync(0xffffffffu, s, o);
        float m2 = s * (1.f / 512.f);
        float v = 0.f;
        #pragma unroll
        for (int j = 0; j < 16; j++) { y[j] -= m2; v += y[j] * y[j]; }
        #pragma unroll
        for (int o = 16; o; o >>= 1) v += __shfl_xor_sync(0xffffffffu, v, o);
        float is = rsqrtf(v * (1.f / 511.f));

        #pragma unroll
        for (int j = 0; j < 16; j++) {
            int n = (j >> 2) * 128 + lane + 32 * (j & 3);
            float nv = cres[j] + y[j] * is + m2;
            g_cur[(size_t)m * Dd + n] = nv;
            if (last) out[(size_t)m * Dd + n] = nv * 0.125f;
        }
    }
}

// ---------------- launch ---------------------------------------------------------
extern "C" void kernel_launch(void* const* d_in, const int* in_sizes, int n_in,
                              void* d_out, int out_size)
{
    const float* x   = (const float*)d_in[0];
    const float* Wq  = (const float*)d_in[1];
    const float* Wk  = (const float*)d_in[2];
    const float* Wvd = (const float*)d_in[3];
    const float* Wvu = (const float*)d_in[4];
    float* out = (float*)d_out;

    const int attn_smem = ASM_T * 4;                     // 52736 B
    const int up_smem   = (2 * WCHUNK + NT * DHh) * 4;   // 71680 B
    cudaFuncSetAttribute(attn_half, cudaFuncAttributeMaxDynamicSharedMemorySize, attn_smem);
    cudaFuncSetAttribute(upnorm_kernel, cudaFuncAttributeMaxDynamicSharedMemorySize, up_smem);

    init_kernel<<<(Sq * Dd / 4) / 256, 256>>>((const float4*)x);
    for (int h = 0; h < Hh; h++) {
        qkv_partial<<<dim3(Sq / 32, 3, NSPLIT), 128>>>(Wq, Wk, Wvd, h);
        qkv_reduce<<<dim3(Sq * DHh / 4 / 256, 3), 256>>>();
        attn_half<<<dim3(Sq / HT, 2), 256, attn_smem>>>();
        upnorm_kernel<<<Sq / NT, 256, up_smem>>>(Wvu, h, h == Hh - 1 ? 1 : 0, out);
    }
}